// round 2
// baseline (speedup 1.0000x reference)
#include <cuda_runtime.h>
#include <cuda_bf16.h>
#include <math.h>

// Problem constants
#define BB 4
#define SS 2048
#define DD 1024
#define HH 16
#define DH 64
#define FF 4096
#define MM (BB*SS)          // 8192 rows

// ---------------------------------------------------------------------------
// Scratch (no cudaMalloc allowed -> __device__ globals)
// ---------------------------------------------------------------------------
__device__ float g_Q  [(size_t)MM*DD];
__device__ float g_K  [(size_t)MM*DD];
__device__ float g_V  [(size_t)MM*DD];
__device__ float g_O  [(size_t)MM*DD];
__device__ float g_T1 [(size_t)MM*DD];
__device__ float g_Y  [(size_t)MM*DD];
__device__ float g_HID[(size_t)MM*FF];

// ---------------------------------------------------------------------------
// Generic tiled GEMM: C[M,N] = A[M,K] @ W + bias (+ residual) (relu optional)
//   headB==0: W is [K,N] row-major
//   headB==1: W is [H][K][64]; column n -> head n>>6, inner n&63 (n0 % 64 == 0)
// Tile 64x64x16, 256 threads, 4x4 per thread.
// ---------------------------------------------------------------------------
__global__ void __launch_bounds__(256) gemm_kernel(
    const float* __restrict__ A, const float* __restrict__ W,
    const float* __restrict__ bias, const float* __restrict__ res,
    float* __restrict__ C, int M, int N, int Kd, int headB, int relu)
{
    __shared__ float As[16][64];   // [k][m] (transposed)
    __shared__ float Bs[16][64];   // [k][n]

    const int tid = threadIdx.x;
    const int m0 = blockIdx.y * 64;
    const int n0 = blockIdx.x * 64;

    const int tx = tid & 15;       // 0..15 -> n
    const int ty = tid >> 4;       // 0..15 -> m

    // load indices
    const int ar = tid >> 2;           // 0..63 (row within A tile)
    const int ac = (tid & 3) * 4;      // 0,4,8,12
    const int br = tid >> 4;           // 0..15 (row within B tile)
    const int bc = (tid & 15) * 4;     // 0..60

    const float* Bbase;
    int bld;
    if (headB) { Bbase = W + (size_t)(n0 >> 6) * (size_t)Kd * 64; bld = 64; }
    else       { Bbase = W + n0;                                   bld = N;  }

    float acc[4][4];
#pragma unroll
    for (int i = 0; i < 4; i++)
#pragma unroll
        for (int j = 0; j < 4; j++) acc[i][j] = 0.f;

    for (int k0 = 0; k0 < Kd; k0 += 16) {
        float4 av = *(const float4*)(A + (size_t)(m0 + ar) * Kd + k0 + ac);
        As[ac + 0][ar] = av.x;
        As[ac + 1][ar] = av.y;
        As[ac + 2][ar] = av.z;
        As[ac + 3][ar] = av.w;
        float4 bv = *(const float4*)(Bbase + (size_t)(k0 + br) * bld + bc);
        *(float4*)&Bs[br][bc] = bv;
        __syncthreads();
#pragma unroll
        for (int kk = 0; kk < 16; kk++) {
            float4 a4 = *(const float4*)&As[kk][ty * 4];
            float4 b4 = *(const float4*)&Bs[kk][tx * 4];
            acc[0][0] += a4.x * b4.x; acc[0][1] += a4.x * b4.y;
            acc[0][2] += a4.x * b4.z; acc[0][3] += a4.x * b4.w;
            acc[1][0] += a4.y * b4.x; acc[1][1] += a4.y * b4.y;
            acc[1][2] += a4.y * b4.z; acc[1][3] += a4.y * b4.w;
            acc[2][0] += a4.z * b4.x; acc[2][1] += a4.z * b4.y;
            acc[2][2] += a4.z * b4.z; acc[2][3] += a4.z * b4.w;
            acc[3][0] += a4.w * b4.x; acc[3][1] += a4.w * b4.y;
            acc[3][2] += a4.w * b4.z; acc[3][3] += a4.w * b4.w;
        }
        __syncthreads();
    }

#pragma unroll
    for (int i = 0; i < 4; i++) {
        const int row = m0 + ty * 4 + i;
        const int col = n0 + tx * 4;
        float4 v;
        v.x = acc[i][0] + bias[col + 0];
        v.y = acc[i][1] + bias[col + 1];
        v.z = acc[i][2] + bias[col + 2];
        v.w = acc[i][3] + bias[col + 3];
        if (res) {
            float4 r4 = *(const float4*)(res + (size_t)row * N + col);
            v.x += r4.x; v.y += r4.y; v.z += r4.z; v.w += r4.w;
        }
        if (relu) {
            v.x = fmaxf(v.x, 0.f); v.y = fmaxf(v.y, 0.f);
            v.z = fmaxf(v.z, 0.f); v.w = fmaxf(v.w, 0.f);
        }
        *(float4*)(C + (size_t)row * N + col) = v;
    }
}

// ---------------------------------------------------------------------------
// Flash attention: Q,K,V stored [B,S,H*DH]; one thread per query row,
// 64 rows per block, online softmax over 32-key tiles.
// Output O in [B,S,H*DH] (heads already concatenated).
// ---------------------------------------------------------------------------
#define FA_BN 32
__global__ void __launch_bounds__(64) flash_kernel(
    const float* __restrict__ Q, const float* __restrict__ Kg,
    const float* __restrict__ Vg, float* __restrict__ O)
{
    __shared__ float Ks[FA_BN][64];
    __shared__ float Vs[FA_BN][64];

    const int t  = threadIdx.x;        // 0..63
    const int bh = blockIdx.y;         // 0..63
    const int b  = bh >> 4;
    const int h  = bh & 15;
    const int qrow = blockIdx.x * 64 + t;

    const size_t rowbase = ((size_t)(b * SS + qrow)) * DD + h * DH;
    const size_t kvhead  = ((size_t)b * SS) * DD + h * DH;

    float qr[64];
#pragma unroll
    for (int e = 0; e < 64; e += 4) {
        float4 v = *(const float4*)(Q + rowbase + e);
        qr[e] = v.x; qr[e+1] = v.y; qr[e+2] = v.z; qr[e+3] = v.w;
    }
    float o[64];
#pragma unroll
    for (int e = 0; e < 64; e++) o[e] = 0.f;
    float m = -1e30f, l = 0.f;

    for (int kt = 0; kt < SS / FA_BN; kt++) {
        // cooperative load of K/V tile: 32x64 floats each
#pragma unroll
        for (int i = 0; i < 8; i++) {
            int f  = t * 8 + i;            // 0..511
            int r  = f >> 4;
            int c4 = (f & 15) << 2;
            size_t g = kvhead + (size_t)(kt * FA_BN + r) * DD + c4;
            *(float4*)(&Ks[r][c4]) = *(const float4*)(Kg + g);
            *(float4*)(&Vs[r][c4]) = *(const float4*)(Vg + g);
        }
        __syncthreads();

        float sc[FA_BN];
        float tmax = -1e30f;
#pragma unroll
        for (int kk = 0; kk < FA_BN; kk++) {
            float s = 0.f;
#pragma unroll
            for (int e = 0; e < 64; e++) s += qr[e] * Ks[kk][e];
            s *= 0.125f;                  // 1/sqrt(64)
            sc[kk] = s;
            tmax = fmaxf(tmax, s);
        }
        float mnew = fmaxf(m, tmax);
        float corr = __expf(m - mnew);
        l *= corr;
#pragma unroll
        for (int e = 0; e < 64; e++) o[e] *= corr;
#pragma unroll
        for (int kk = 0; kk < FA_BN; kk++) {
            float p = __expf(sc[kk] - mnew);
            l += p;
#pragma unroll
            for (int e = 0; e < 64; e++) o[e] += p * Vs[kk][e];
        }
        m = mnew;
        __syncthreads();
    }

    const float inv = 1.f / l;
#pragma unroll
    for (int e = 0; e < 64; e += 4) {
        float4 v = make_float4(o[e] * inv, o[e+1] * inv, o[e+2] * inv, o[e+3] * inv);
        *(float4*)(O + rowbase + e) = v;
    }
}

// ---------------------------------------------------------------------------
// Row LayerNorm over D=1024, one block (256 thr) per row.
// ---------------------------------------------------------------------------
__global__ void __launch_bounds__(256) ln_kernel(
    const float* __restrict__ X, const float* __restrict__ g,
    const float* __restrict__ bta, float* __restrict__ Y)
{
    __shared__ float red[256];
    const int row = blockIdx.x;
    const int t = threadIdx.x;
    const float* xr = X + (size_t)row * DD;

    float4 v = *(const float4*)(xr + t * 4);
    red[t] = v.x + v.y + v.z + v.w;
    __syncthreads();
    for (int off = 128; off > 0; off >>= 1) {
        if (t < off) red[t] += red[t + off];
        __syncthreads();
    }
    float mu = red[0] * (1.f / 1024.f);
    __syncthreads();

    float dx = v.x - mu, dy = v.y - mu, dz = v.z - mu, dw = v.w - mu;
    red[t] = dx * dx + dy * dy + dz * dz + dw * dw;
    __syncthreads();
    for (int off = 128; off > 0; off >>= 1) {
        if (t < off) red[t] += red[t + off];
        __syncthreads();
    }
    float var = red[0] * (1.f / 1024.f);
    float rstd = rsqrtf(var + 1e-5f);

    float4 gg = *(const float4*)(g + t * 4);
    float4 bb = *(const float4*)(bta + t * 4);
    float4 out;
    out.x = dx * rstd * gg.x + bb.x;
    out.y = dy * rstd * gg.y + bb.y;
    out.z = dz * rstd * gg.z + bb.z;
    out.w = dw * rstd * gg.w + bb.w;
    *(float4*)(Y + (size_t)row * DD + t * 4) = out;
}

// ---------------------------------------------------------------------------
// Launch
// ---------------------------------------------------------------------------
extern "C" void kernel_launch(void* const* d_in, const int* in_sizes, int n_in,
                              void* d_out, int out_size)
{
    const float* x    = (const float*)d_in[0];
    const float* wq   = (const float*)d_in[1];
    const float* bq   = (const float*)d_in[2];
    const float* wk   = (const float*)d_in[3];
    const float* bk   = (const float*)d_in[4];
    const float* wv   = (const float*)d_in[5];
    const float* bv   = (const float*)d_in[6];
    const float* wo   = (const float*)d_in[7];
    const float* bo   = (const float*)d_in[8];
    const float* ln1g = (const float*)d_in[9];
    const float* ln1b = (const float*)d_in[10];
    const float* w1   = (const float*)d_in[11];
    const float* b1   = (const float*)d_in[12];
    const float* w2   = (const float*)d_in[13];
    const float* b2   = (const float*)d_in[14];
    const float* ln2g = (const float*)d_in[15];
    const float* ln2b = (const float*)d_in[16];
    float* out = (float*)d_out;

    float *Q, *K, *V, *O, *T1, *Y, *HID;
    cudaGetSymbolAddress((void**)&Q,   g_Q);
    cudaGetSymbolAddress((void**)&K,   g_K);
    cudaGetSymbolAddress((void**)&V,   g_V);
    cudaGetSymbolAddress((void**)&O,   g_O);
    cudaGetSymbolAddress((void**)&T1,  g_T1);
    cudaGetSymbolAddress((void**)&Y,   g_Y);
    cudaGetSymbolAddress((void**)&HID, g_HID);

    dim3 gProj(DD / 64, MM / 64);      // (16,128)
    dim3 gFfn1(FF / 64, MM / 64);      // (64,128)

    // QKV projections (head-blocked weights), output [B,S,H*DH]
    gemm_kernel<<<gProj, 256>>>(x, wq, bq, nullptr, Q, MM, DD, DD, 1, 0);
    gemm_kernel<<<gProj, 256>>>(x, wk, bk, nullptr, K, MM, DD, DD, 1, 0);
    gemm_kernel<<<gProj, 256>>>(x, wv, bv, nullptr, V, MM, DD, DD, 1, 0);

    // Attention
    flash_kernel<<<dim3(SS / 64, BB * HH), 64>>>(Q, K, V, O);

    // Output projection + residual(x), then LN1 -> Y
    gemm_kernel<<<gProj, 256>>>(O, wo, bo, x, T1, MM, DD, DD, 0, 0);
    ln_kernel<<<MM, 256>>>(T1, ln1g, ln1b, Y);

    // FFN
    gemm_kernel<<<gFfn1, 256>>>(Y, w1, b1, nullptr, HID, MM, FF, DD, 0, 1);
    gemm_kernel<<<gProj, 256>>>(HID, w2, b2, Y, T1, MM, DD, FF, 0, 0);
    ln_kernel<<<MM, 256>>>(T1, ln2g, ln2b, out);
}

// round 6
// speedup vs baseline: 2.1113x; 2.1113x over previous
#include <cuda_runtime.h>
#include <cuda_fp16.h>
#include <cstdint>
#include <math.h>

// Problem constants
#define BB 4
#define SS 2048
#define DD 1024
#define HH 16
#define DH 64
#define FF 4096
#define MM (BB*SS)          // 8192 rows

// ---------------------------------------------------------------------------
// Scratch (__device__ globals; no cudaMalloc allowed)
// ---------------------------------------------------------------------------
__device__ __half g_xh [(size_t)MM*DD];
__device__ __half g_wqT[(size_t)DD*DD];
__device__ __half g_wkT[(size_t)DD*DD];
__device__ __half g_wvT[(size_t)DD*DD];
__device__ __half g_woT[(size_t)DD*DD];
__device__ __half g_w1T[(size_t)DD*FF];
__device__ __half g_w2T[(size_t)DD*FF];
__device__ float  g_Q  [(size_t)MM*DD];
__device__ float  g_K  [(size_t)MM*DD];
__device__ float  g_V  [(size_t)MM*DD];
__device__ __half g_Oh [(size_t)MM*DD];
__device__ float  g_T1 [(size_t)MM*DD];
__device__ float  g_Y  [(size_t)MM*DD];
__device__ __half g_Yh [(size_t)MM*DD];
__device__ __half g_Hh [(size_t)MM*FF];

// ---------------------------------------------------------------------------
// Helpers
// ---------------------------------------------------------------------------
__device__ __forceinline__ uint32_t smem_u32(const void* p) {
    uint32_t a;
    asm("{ .reg .u64 t; cvta.to.shared.u64 t, %1; cvt.u32.u64 %0, t; }"
        : "=r"(a) : "l"(p));
    return a;
}
__device__ __forceinline__ uint32_t pack_h2(float a, float b) {
    __half2 h = __floats2half2_rn(a, b);
    return *(uint32_t*)&h;
}

#define CP_ASYNC16(dst, src) \
    asm volatile("cp.async.cg.shared.global [%0], [%1], 16;" :: "r"(dst), "l"(src))
#define CP_COMMIT() asm volatile("cp.async.commit_group;")
#define CP_WAIT1()  asm volatile("cp.async.wait_group 1;")

#define LDM_X4(r0, r1, r2, r3, addr)                                    \
    asm volatile("ldmatrix.sync.aligned.m8n8.x4.shared.b16 "            \
                 "{%0,%1,%2,%3}, [%4];"                                 \
                 : "=r"(r0), "=r"(r1), "=r"(r2), "=r"(r3) : "r"(addr))

#define MMA16816(d, a, b)                                               \
    asm volatile("mma.sync.aligned.m16n8k16.row.col.f32.f16.f16.f32 "   \
                 "{%0,%1,%2,%3}, {%4,%5,%6,%7}, {%8,%9}, {%0,%1,%2,%3};"\
                 : "+f"((d)[0]), "+f"((d)[1]), "+f"((d)[2]), "+f"((d)[3])\
                 : "r"((a)[0]), "r"((a)[1]), "r"((a)[2]), "r"((a)[3]),  \
                   "r"((b)[0]), "r"((b)[1]))

// Swizzled byte offset within a 128x32-half tile (row = 64B, 4 x 16B chunks)
__device__ __forceinline__ uint32_t tile_off(int row, int chunk) {
    return (uint32_t)(row * 64 + ((chunk ^ ((row >> 1) & 3)) << 4));
}

// ---------------------------------------------------------------------------
// HMMA GEMM: C[M,N](+bias,+res,relu) = A[M,Kd] @ Bw^T;  A,Bw fp16, Bw is [N,Kd].
// Block 128x128, BK=32, 8 warps (2x4), warp tile 64x32, mma m16n8k16.
// ---------------------------------------------------------------------------
__global__ void __launch_bounds__(256) gemm_hmma(
    const __half* __restrict__ A, const __half* __restrict__ Bw,
    const float* __restrict__ bias, const float* __restrict__ res,
    float* __restrict__ C, __half* __restrict__ Ch,
    int Kd, int N, int relu)
{
    __shared__ __align__(16) char smem[32768];  // 2 bufs x (A 8KB + B 8KB)

    const int tid  = threadIdx.x;
    const int lane = tid & 31;
    const int wid  = tid >> 5;
    const int m0 = blockIdx.y * 128, n0 = blockIdx.x * 128;
    const int wm = (wid >> 2) * 64;      // 0 / 64
    const int wn = (wid & 3) * 32;       // 0..96

    const uint32_t sbase = smem_u32(smem);

    // --- global->smem load mapping (per thread: 2x16B for A, 2x16B for B) ---
    const int grow   = tid >> 1;          // 0..127
    const int gchk0  = (tid & 1) * 2;     // 0 or 2
    const uint32_t dA0 = tile_off(grow, gchk0);
    const uint32_t dA1 = tile_off(grow, gchk0 + 1);
    const __half* Asrc = A  + (size_t)(m0 + grow) * Kd + gchk0 * 8;
    const __half* Bsrc = Bw + (size_t)(n0 + grow) * Kd + gchk0 * 8;

    // --- ldmatrix lane addressing ---
    const int a_row = wm + (lane & 15);
    const int a_chk = lane >> 4;                       // 0/1
    const int a_swz = (a_row >> 1) & 3;
    const int b_row = wn + (lane & 7) + ((lane & 16) >> 1);
    const int b_chk = (lane >> 3) & 1;
    const int b_swz = (b_row >> 1) & 3;

    float acc[4][4][4];
#pragma unroll
    for (int i = 0; i < 4; i++)
#pragma unroll
        for (int j = 0; j < 4; j++)
#pragma unroll
            for (int r = 0; r < 4; r++) acc[i][j][r] = 0.f;

    const int nIter = Kd >> 5;

    // issue tile 0
    {
        uint32_t ab = sbase, bb = sbase + 8192u;
        CP_ASYNC16(ab + dA0, Asrc);
        CP_ASYNC16(ab + dA1, Asrc + 8);
        CP_ASYNC16(bb + dA0, Bsrc);
        CP_ASYNC16(bb + dA1, Bsrc + 8);
    }
    CP_COMMIT();

    for (int it = 0; it < nIter; ++it) {
        if (it + 1 < nIter) {
            const int nb = (it + 1) & 1;
            uint32_t ab = sbase + nb * 16384u, bb = ab + 8192u;
            const __half* as = Asrc + (size_t)(it + 1) * 32;
            const __half* bs = Bsrc + (size_t)(it + 1) * 32;
            CP_ASYNC16(ab + dA0, as);
            CP_ASYNC16(ab + dA1, as + 8);
            CP_ASYNC16(bb + dA0, bs);
            CP_ASYNC16(bb + dA1, bs + 8);
        }
        CP_COMMIT();
        CP_WAIT1();
        __syncthreads();

        const int buf = it & 1;
        const uint32_t ab = sbase + buf * 16384u;
        const uint32_t bb = ab + 8192u;
        const uint32_t aAddrBase = ab + (uint32_t)a_row * 64;
        const uint32_t bAddrBase = bb + (uint32_t)b_row * 64;

#pragma unroll
        for (int ks = 0; ks < 2; ks++) {
            const int kc = ks * 2;
            uint32_t afr[4][4];
            uint32_t bfr[4][2];
#pragma unroll
            for (int mi = 0; mi < 4; mi++) {
                uint32_t ad = aAddrBase + mi * 1024u
                            + (uint32_t)(((a_chk + kc) ^ a_swz) << 4);
                LDM_X4(afr[mi][0], afr[mi][1], afr[mi][2], afr[mi][3], ad);
            }
#pragma unroll
            for (int np = 0; np < 2; np++) {
                uint32_t bd = bAddrBase + np * 1024u
                            + (uint32_t)(((b_chk + kc) ^ b_swz) << 4);
                LDM_X4(bfr[np*2][0], bfr[np*2][1], bfr[np*2+1][0], bfr[np*2+1][1], bd);
            }
#pragma unroll
            for (int mi = 0; mi < 4; mi++)
#pragma unroll
                for (int ni = 0; ni < 4; ni++)
                    MMA16816(acc[mi][ni], afr[mi], bfr[ni]);
        }
        __syncthreads();
    }

    // --- epilogue ---
    const int lane4 = lane >> 2;           // 0..7
    const int lcol  = (lane & 3) * 2;
    float2 bv[4];
#pragma unroll
    for (int ni = 0; ni < 4; ni++) {
        int cc = n0 + wn + ni * 8 + lcol;
        bv[ni] = *(const float2*)(bias + cc);
    }
#pragma unroll
    for (int mi = 0; mi < 4; mi++) {
#pragma unroll
        for (int hf = 0; hf < 2; hf++) {
            const int row = m0 + wm + mi * 16 + lane4 + hf * 8;
#pragma unroll
            for (int ni = 0; ni < 4; ni++) {
                const int cc = n0 + wn + ni * 8 + lcol;
                float vx = acc[mi][ni][hf*2+0] + bv[ni].x;
                float vy = acc[mi][ni][hf*2+1] + bv[ni].y;
                if (res) {
                    float2 rr = *(const float2*)(res + (size_t)row * N + cc);
                    vx += rr.x; vy += rr.y;
                }
                if (relu) { vx = fmaxf(vx, 0.f); vy = fmaxf(vy, 0.f); }
                if (C) *(float2*)(C + (size_t)row * N + cc) = make_float2(vx, vy);
                if (Ch) {
                    uint32_t h = pack_h2(vx, vy);
                    *(uint32_t*)(Ch + (size_t)row * N + cc) = h;
                }
            }
        }
    }
}

// ---------------------------------------------------------------------------
// Tiled transpose + f32->f16: out[(z*C + c)*R + r] = in[z*R*C + r*C + c]
// ---------------------------------------------------------------------------
__global__ void __launch_bounds__(256) transpose_h(
    const float* __restrict__ in, __half* __restrict__ out, int R, int C)
{
    __shared__ float t[32][33];
    const int z = blockIdx.z;
    const float* ip = in + (size_t)z * R * C;
    const int r0 = blockIdx.y * 32, c0 = blockIdx.x * 32;
    const int tx = threadIdx.x, ty = threadIdx.y;
#pragma unroll
    for (int j = 0; j < 32; j += 8)
        t[ty + j][tx] = ip[(size_t)(r0 + ty + j) * C + c0 + tx];
    __syncthreads();
#pragma unroll
    for (int j = 0; j < 32; j += 8)
        out[((size_t)z * C + c0 + ty + j) * R + r0 + tx] = __float2half(t[tx][ty + j]);
}

__global__ void __launch_bounds__(256) f2h_kernel(
    const float* __restrict__ in, __half* __restrict__ out)
{
    int i = blockIdx.x * blockDim.x + threadIdx.x;
    float2 v = ((const float2*)in)[i];
    ((__half2*)out)[i] = __floats2half2_rn(v.x, v.y);
}

// ---------------------------------------------------------------------------
// Flash attention (fp32 compute, fp16 output). Q,K,V: [B,S,H*DH] fp32.
// ---------------------------------------------------------------------------
#define FA_BN 32
__global__ void __launch_bounds__(64) flash_kernel(
    const float* __restrict__ Q, const float* __restrict__ Kg,
    const float* __restrict__ Vg, __half* __restrict__ Oh)
{
    __shared__ float Ks[FA_BN][64];
    __shared__ float Vs[FA_BN][64];

    const int t  = threadIdx.x;
    const int bh = blockIdx.y;
    const int b  = bh >> 4;
    const int h  = bh & 15;
    const int qrow = blockIdx.x * 64 + t;

    const size_t rowbase = ((size_t)(b * SS + qrow)) * DD + h * DH;
    const size_t kvhead  = ((size_t)b * SS) * DD + h * DH;

    float qr[64];
#pragma unroll
    for (int e = 0; e < 64; e += 4) {
        float4 v = *(const float4*)(Q + rowbase + e);
        qr[e] = v.x; qr[e+1] = v.y; qr[e+2] = v.z; qr[e+3] = v.w;
    }
    float o[64];
#pragma unroll
    for (int e = 0; e < 64; e++) o[e] = 0.f;
    float m = -1e30f, l = 0.f;

    for (int kt = 0; kt < SS / FA_BN; kt++) {
#pragma unroll
        for (int i = 0; i < 8; i++) {
            int f  = t * 8 + i;
            int r  = f >> 4;
            int c4 = (f & 15) << 2;
            size_t g = kvhead + (size_t)(kt * FA_BN + r) * DD + c4;
            *(float4*)(&Ks[r][c4]) = *(const float4*)(Kg + g);
            *(float4*)(&Vs[r][c4]) = *(const float4*)(Vg + g);
        }
        __syncthreads();

        float sc[FA_BN];
        float tmax = -1e30f;
#pragma unroll
        for (int kk = 0; kk < FA_BN; kk++) {
            float s = 0.f;
#pragma unroll
            for (int e = 0; e < 64; e++) s += qr[e] * Ks[kk][e];
            s *= 0.125f;
            sc[kk] = s;
            tmax = fmaxf(tmax, s);
        }
        float mnew = fmaxf(m, tmax);
        float corr = __expf(m - mnew);
        l *= corr;
#pragma unroll
        for (int e = 0; e < 64; e++) o[e] *= corr;
#pragma unroll
        for (int kk = 0; kk < FA_BN; kk++) {
            float p = __expf(sc[kk] - mnew);
            l += p;
#pragma unroll
            for (int e = 0; e < 64; e++) o[e] += p * Vs[kk][e];
        }
        m = mnew;
        __syncthreads();
    }

    const float inv = 1.f / l;
#pragma unroll
    for (int e = 0; e < 64; e += 8) {
        uint4 u = make_uint4(pack_h2(o[e+0]*inv, o[e+1]*inv), pack_h2(o[e+2]*inv, o[e+3]*inv),
                             pack_h2(o[e+4]*inv, o[e+5]*inv), pack_h2(o[e+6]*inv, o[e+7]*inv));
        *(uint4*)(Oh + rowbase + e) = u;
    }
}

// ---------------------------------------------------------------------------
// LayerNorm over D=1024; fp32 out + optional fp16 out.
// ---------------------------------------------------------------------------
__global__ void __launch_bounds__(256) ln_kernel(
    const float* __restrict__ X, const float* __restrict__ g,
    const float* __restrict__ bta, float* __restrict__ Y, __half* __restrict__ Yh)
{
    __shared__ float red[256];
    const int row = blockIdx.x;
    const int t = threadIdx.x;
    const float* xr = X + (size_t)row * DD;

    float4 v = *(const float4*)(xr + t * 4);
    red[t] = v.x + v.y + v.z + v.w;
    __syncthreads();
    for (int off = 128; off > 0; off >>= 1) {
        if (t < off) red[t] += red[t + off];
        __syncthreads();
    }
    float mu = red[0] * (1.f / 1024.f);
    __syncthreads();

    float dx = v.x - mu, dy = v.y - mu, dz = v.z - mu, dw = v.w - mu;
    red[t] = dx * dx + dy * dy + dz * dz + dw * dw;
    __syncthreads();
    for (int off = 128; off > 0; off >>= 1) {
        if (t < off) red[t] += red[t + off];
        __syncthreads();
    }
    float var = red[0] * (1.f / 1024.f);
    float rstd = rsqrtf(var + 1e-5f);

    float4 gg = *(const float4*)(g + t * 4);
    float4 bb = *(const float4*)(bta + t * 4);
    float4 outv;
    outv.x = dx * rstd * gg.x + bb.x;
    outv.y = dy * rstd * gg.y + bb.y;
    outv.z = dz * rstd * gg.z + bb.z;
    outv.w = dw * rstd * gg.w + bb.w;
    *(float4*)(Y + (size_t)row * DD + t * 4) = outv;
    if (Yh) {
        uint2 u = make_uint2(pack_h2(outv.x, outv.y), pack_h2(outv.z, outv.w));
        *(uint2*)(Yh + (size_t)row * DD + t * 4) = u;
    }
}

// ---------------------------------------------------------------------------
// Launch
// ---------------------------------------------------------------------------
extern "C" void kernel_launch(void* const* d_in, const int* in_sizes, int n_in,
                              void* d_out, int out_size)
{
    const float* x    = (const float*)d_in[0];
    const float* wq   = (const float*)d_in[1];
    const float* bq   = (const float*)d_in[2];
    const float* wk   = (const float*)d_in[3];
    const float* bk   = (const float*)d_in[4];
    const float* wv   = (const float*)d_in[5];
    const float* bv   = (const float*)d_in[6];
    const float* wo   = (const float*)d_in[7];
    const float* bo   = (const float*)d_in[8];
    const float* ln1g = (const float*)d_in[9];
    const float* ln1b = (const float*)d_in[10];
    const float* w1   = (const float*)d_in[11];
    const float* b1   = (const float*)d_in[12];
    const float* w2   = (const float*)d_in[13];
    const float* b2   = (const float*)d_in[14];
    const float* ln2g = (const float*)d_in[15];
    const float* ln2b = (const float*)d_in[16];
    float* out = (float*)d_out;

    __half *xh, *wqT, *wkT, *wvT, *woT, *w1T, *w2T, *Oh, *Yh, *Hh;
    float *Q, *K, *V, *T1, *Y;
    cudaGetSymbolAddress((void**)&xh,  g_xh);
    cudaGetSymbolAddress((void**)&wqT, g_wqT);
    cudaGetSymbolAddress((void**)&wkT, g_wkT);
    cudaGetSymbolAddress((void**)&wvT, g_wvT);
    cudaGetSymbolAddress((void**)&woT, g_woT);
    cudaGetSymbolAddress((void**)&w1T, g_w1T);
    cudaGetSymbolAddress((void**)&w2T, g_w2T);
    cudaGetSymbolAddress((void**)&Q,   g_Q);
    cudaGetSymbolAddress((void**)&K,   g_K);
    cudaGetSymbolAddress((void**)&V,   g_V);
    cudaGetSymbolAddress((void**)&Oh,  g_Oh);
    cudaGetSymbolAddress((void**)&T1,  g_T1);
    cudaGetSymbolAddress((void**)&Y,   g_Y);
    cudaGetSymbolAddress((void**)&Yh,  g_Yh);
    cudaGetSymbolAddress((void**)&Hh,  g_Hh);

    // --- weight prep (transposed fp16 [N,K]) + activation convert ---
    f2h_kernel<<<(MM * DD / 2) / 256, 256>>>(x, xh);
    transpose_h<<<dim3(DH/32, DD/32, HH), dim3(32,8)>>>(wq, wqT, DD, DH);
    transpose_h<<<dim3(DH/32, DD/32, HH), dim3(32,8)>>>(wk, wkT, DD, DH);
    transpose_h<<<dim3(DH/32, DD/32, HH), dim3(32,8)>>>(wv, wvT, DD, DH);
    transpose_h<<<dim3(DD/32, DD/32, 1),  dim3(32,8)>>>(wo, woT, DD, DD);
    transpose_h<<<dim3(FF/32, DD/32, 1),  dim3(32,8)>>>(w1, w1T, DD, FF);
    transpose_h<<<dim3(DD/32, FF/32, 1),  dim3(32,8)>>>(w2, w2T, FF, DD);

    dim3 gD(DD/128, MM/128);   // (8, 64)
    dim3 gF(FF/128, MM/128);   // (32, 64)

    // QKV projections (fp32 out for flash)
    gemm_hmma<<<gD, 256>>>(xh, wqT, bq, nullptr, Q, nullptr, DD, DD, 0);
    gemm_hmma<<<gD, 256>>>(xh, wkT, bk, nullptr, K, nullptr, DD, DD, 0);
    gemm_hmma<<<gD, 256>>>(xh, wvT, bv, nullptr, V, nullptr, DD, DD, 0);

    // Attention -> fp16 O
    flash_kernel<<<dim3(SS/64, BB*HH), 64>>>(Q, K, V, Oh);

    // O-proj + residual(x) -> T1; LN1 -> Y (fp32) + Yh (fp16)
    gemm_hmma<<<gD, 256>>>(Oh, woT, bo, x, T1, nullptr, DD, DD, 0);
    ln_kernel<<<MM, 256>>>(T1, ln1g, ln1b, Y, Yh);

    // FFN
    gemm_hmma<<<gF, 256>>>(Yh, w1T, b1, nullptr, nullptr, Hh, DD, FF, 1);
    gemm_hmma<<<gD, 256>>>(Hh, w2T, b2, Y, T1, nullptr, FF, DD, 0);
    ln_kernel<<<MM, 256>>>(T1, ln2g, ln2b, out, nullptr);
}